// round 1
// baseline (speedup 1.0000x reference)
#include <cuda_runtime.h>

typedef unsigned long long ull;

#define SQ   2048
#define DH   64
#define NBLK 32

// ---- packed f32x2 helpers (sm_100+) ----
__device__ __forceinline__ ull pack2(float lo, float hi) {
    ull r; asm("mov.b64 %0, {%1, %2};" : "=l"(r) : "f"(lo), "f"(hi)); return r;
}
__device__ __forceinline__ void unpack2(ull v, float& lo, float& hi) {
    asm("mov.b64 {%0, %1}, %2;" : "=f"(lo), "=f"(hi) : "l"(v));
}
__device__ __forceinline__ void fma2(ull& d, ull a, ull b) {
    asm("fma.rn.f32x2 %0, %1, %2, %0;" : "+l"(d) : "l"(a), "l"(b));
}
__device__ __forceinline__ void mul2(ull& d, ull a) {
    asm("mul.rn.f32x2 %0, %0, %1;" : "+l"(d) : "l"(a));
}

// Block-sparse flash attention.
// Grid: (32 q-blocks, B*H). Block: 128 threads.
// Thread map (both GEMMs): qg = tid>>4 (8 groups of 8 q-rows), kg = tid&15
// (4 k-cols in S-GEMM / 4 d-cols in PV-GEMM).
// f32x2 pairs run along q: pairs load directly with LDS.64 from transposed,
// XOR-swizzled smem tiles (conflict-free in the compute loops).
__global__ void __launch_bounds__(128)
bma_attn(const float* __restrict__ Q, const float* __restrict__ K,
         const float* __restrict__ V, const float* __restrict__ Mk,
         const int* __restrict__ Mat, float* __restrict__ Out)
{
    // exactly 48KB static smem; KPS holds K^T during S-GEMM, then P^T during PV
    __shared__ float QtS[64*64];
    __shared__ float KPS[64*64];
    __shared__ float VsS[64*64];

    const int tid = threadIdx.x;
    const int qg  = tid >> 4;   // 0..7
    const int kg  = tid & 15;   // 0..15
    const int qb  = blockIdx.x;
    const int bh  = blockIdx.y;
    const int b   = bh >> 3;    // H = 8

    const float* Qp     = Q + ((size_t)bh * SQ + (size_t)qb * 64) * DH;
    const float* Kbh    = K + (size_t)bh * SQ * DH;
    const float* Vbh    = V + (size_t)bh * SQ * DH;
    const float* mrow   = Mk + (size_t)b * SQ;
    const int*   matrow = Mat + qb * NBLK;

    // ---- load Q tile, transposed + swizzled: Qt[d][q'], q4' = q4 ^ (d>>2) ----
    #pragma unroll
    for (int it = 0; it < 8; ++it) {
        int row = qg + it * 8;                                  // q row 0..63
        float4 qv = *(const float4*)(Qp + row * DH + kg * 4);   // coalesced
        float qa[4] = {qv.x, qv.y, qv.z, qv.w};
        int c = row >> 2, qr = row & 3;
        #pragma unroll
        for (int i = 0; i < 4; ++i) {
            int d = kg * 4 + i;
            QtS[d * 64 + ((c ^ kg) << 2) + qr] = qa[i];         // conflict-free
        }
    }

    float m[8], l[8];
    #pragma unroll
    for (int i = 0; i < 8; ++i) { m[i] = -1e30f; l[i] = 0.f; }
    ull o[4][4];                                                // O pairs-along-q
    #pragma unroll
    for (int a = 0; a < 4; ++a)
        #pragma unroll
        for (int j = 0; j < 4; ++j) o[a][j] = 0ull;

    for (int kb = 0; kb < NBLK; ++kb) {
        if (matrow[kb] == 0) continue;                          // block-skip (uniform)
        const float* Kp = Kbh + (size_t)kb * 64 * DH;
        const float* Vp = Vbh + (size_t)kb * 64 * DH;

        __syncthreads();   // previous PV finished reading KPS(P^T)/VsS
        // ---- load K^T (swizzled) + V (row-major) ----
        #pragma unroll
        for (int it = 0; it < 8; ++it) {
            int row = qg + it * 8;
            float4 kv = *(const float4*)(Kp + row * DH + kg * 4);
            float ka[4] = {kv.x, kv.y, kv.z, kv.w};
            int c = row >> 2, qr = row & 3;
            #pragma unroll
            for (int i = 0; i < 4; ++i) {
                int d = kg * 4 + i;
                KPS[d * 64 + ((c ^ kg) << 2) + qr] = ka[i];
            }
            int idx = tid + it * 128;
            int vr = idx >> 4, vc = idx & 15;
            *(float4*)&VsS[vr * 64 + vc * 4] =
                *(const float4*)(Vp + vr * DH + vc * 4);
        }
        __syncthreads();

        // ---- S = Q @ K^T : 64 rank-1 steps, 16 FMA2/step/thread ----
        ull s[4][4];
        #pragma unroll
        for (int a = 0; a < 4; ++a)
            #pragma unroll
            for (int j = 0; j < 4; ++j) s[a][j] = 0ull;

        #pragma unroll 4
        for (int d = 0; d < 64; ++d) {
            const float* rowp = &QtS[d * 64];
            int sw = d >> 2;
            int c0 = ((qg * 2)     ^ sw) << 2;
            int c1 = ((qg * 2 + 1) ^ sw) << 2;
            ull q01 = *(const ull*)(rowp + c0);
            ull q23 = *(const ull*)(rowp + c0 + 2);
            ull q45 = *(const ull*)(rowp + c1);
            ull q67 = *(const ull*)(rowp + c1 + 2);
            float4 kv = *(const float4*)&KPS[d * 64 + ((kg ^ sw) << 2)];
            ull k0 = pack2(kv.x, kv.x), k1 = pack2(kv.y, kv.y);
            ull k2 = pack2(kv.z, kv.z), k3 = pack2(kv.w, kv.w);
            fma2(s[0][0], q01, k0); fma2(s[0][1], q01, k1);
            fma2(s[0][2], q01, k2); fma2(s[0][3], q01, k3);
            fma2(s[1][0], q23, k0); fma2(s[1][1], q23, k1);
            fma2(s[1][2], q23, k2); fma2(s[1][3], q23, k3);
            fma2(s[2][0], q45, k0); fma2(s[2][1], q45, k1);
            fma2(s[2][2], q45, k2); fma2(s[2][3], q45, k3);
            fma2(s[3][0], q67, k0); fma2(s[3][1], q67, k1);
            fma2(s[3][2], q67, k2); fma2(s[3][3], q67, k3);
        }

        // ---- online softmax ----
        float p[8][4];
        #pragma unroll
        for (int a = 0; a < 4; ++a)
            #pragma unroll
            for (int j = 0; j < 4; ++j)
                unpack2(s[a][j], p[2*a][j], p[2*a+1][j]);

        // additive padding-mask bias: 1e6*(mask-1)
        float4 mb = *(const float4*)(mrow + kb * 64 + kg * 4);
        float bb[4] = {(mb.x - 1.f) * 1e6f, (mb.y - 1.f) * 1e6f,
                       (mb.z - 1.f) * 1e6f, (mb.w - 1.f) * 1e6f};

        float sf[8];
        #pragma unroll
        for (int qi = 0; qi < 8; ++qi) {
            #pragma unroll
            for (int j = 0; j < 4; ++j) p[qi][j] += bb[j];
            float r = fmaxf(fmaxf(p[qi][0], p[qi][1]), fmaxf(p[qi][2], p[qi][3]));
            #pragma unroll
            for (int off = 8; off > 0; off >>= 1)
                r = fmaxf(r, __shfl_xor_sync(0xffffffffu, r, off, 16));
            float mn = fmaxf(m[qi], r);
            sf[qi] = __expf(m[qi] - mn);
            m[qi] = mn;
            float rs = 0.f;
            #pragma unroll
            for (int j = 0; j < 4; ++j) { p[qi][j] = __expf(p[qi][j] - mn); rs += p[qi][j]; }
            #pragma unroll
            for (int off = 8; off > 0; off >>= 1)
                rs += __shfl_xor_sync(0xffffffffu, rs, off, 16);
            l[qi] = l[qi] * sf[qi] + rs;
        }

        __syncthreads();   // everyone done reading K^T from KPS
        // ---- write P^T into KPS (swizzled, 2-way STS worst case) ----
        #pragma unroll
        for (int qi = 0; qi < 8; ++qi) {
            int q = qg * 8 + qi;
            int c = q >> 2, qr = q & 3;
            #pragma unroll
            for (int j = 0; j < 4; ++j) {
                int k = kg * 4 + j;
                KPS[k * 64 + ((c ^ (k >> 2)) << 2) + qr] = p[qi][j];
            }
        }
        __syncthreads();

        // ---- rescale O, then O += P @ V ----
        ull sp0 = pack2(sf[0], sf[1]), sp1 = pack2(sf[2], sf[3]);
        ull sp2 = pack2(sf[4], sf[5]), sp3 = pack2(sf[6], sf[7]);
        #pragma unroll
        for (int j = 0; j < 4; ++j) {
            mul2(o[0][j], sp0); mul2(o[1][j], sp1);
            mul2(o[2][j], sp2); mul2(o[3][j], sp3);
        }

        #pragma unroll 4
        for (int ks = 0; ks < 64; ++ks) {
            const float* rowp = &KPS[ks * 64];
            int sw = ks >> 2;
            int c0 = ((qg * 2)     ^ sw) << 2;
            int c1 = ((qg * 2 + 1) ^ sw) << 2;
            ull p01 = *(const ull*)(rowp + c0);
            ull p23 = *(const ull*)(rowp + c0 + 2);
            ull p45 = *(const ull*)(rowp + c1);
            ull p67 = *(const ull*)(rowp + c1 + 2);
            float4 vv = *(const float4*)&VsS[ks * 64 + kg * 4];
            ull v0 = pack2(vv.x, vv.x), v1 = pack2(vv.y, vv.y);
            ull v2 = pack2(vv.z, vv.z), v3 = pack2(vv.w, vv.w);
            fma2(o[0][0], p01, v0); fma2(o[0][1], p01, v1);
            fma2(o[0][2], p01, v2); fma2(o[0][3], p01, v3);
            fma2(o[1][0], p23, v0); fma2(o[1][1], p23, v1);
            fma2(o[1][2], p23, v2); fma2(o[1][3], p23, v3);
            fma2(o[2][0], p45, v0); fma2(o[2][1], p45, v1);
            fma2(o[2][2], p45, v2); fma2(o[2][3], p45, v3);
            fma2(o[3][0], p67, v0); fma2(o[3][1], p67, v1);
            fma2(o[3][2], p67, v2); fma2(o[3][3], p67, v3);
        }
    }

    // ---- epilogue: O / l, coalesced float4 stores ----
    float ov[8][4];
    #pragma unroll
    for (int a = 0; a < 4; ++a)
        #pragma unroll
        for (int j = 0; j < 4; ++j)
            unpack2(o[a][j], ov[2*a][j], ov[2*a+1][j]);

    #pragma unroll
    for (int qi = 0; qi < 8; ++qi) {
        float inv = 1.f / l[qi];
        int row = qb * 64 + qg * 8 + qi;
        float4 r = make_float4(ov[qi][0] * inv, ov[qi][1] * inv,
                               ov[qi][2] * inv, ov[qi][3] * inv);
        *(float4*)(Out + ((size_t)bh * SQ + row) * DH + kg * 4) = r;
    }
}

extern "C" void kernel_launch(void* const* d_in, const int* in_sizes, int n_in,
                              void* d_out, int out_size)
{
    const float* q    = (const float*)d_in[0];
    const float* k    = (const float*)d_in[1];
    const float* v    = (const float*)d_in[2];
    const float* mask = (const float*)d_in[3];
    const int*   mat  = (const int*)  d_in[4];
    float* out = (float*)d_out;

    dim3 grid(NBLK, 16);   // 32 q-blocks x (B*H = 16)
    bma_attn<<<grid, 128>>>(q, k, v, mask, mat, out);
}